// round 3
// baseline (speedup 1.0000x reference)
#include <cuda_runtime.h>
#include <cuda_bf16.h>
#include <math.h>

// Problem constants
#define BATCH 1024
#define ZDIM  512
#define ADIM  8
#define AH    64
#define ZH    512
#define NNEG  100           // shifts 1..99 -> 99 extra columns
#define NCOLS 1123          // 1024 + 99
#define LDSIM 1152          // padded row stride for sim_mat

typedef unsigned long long ull;

// packed dual-FMA: d = a * b + d  (two fp32 lanes per instruction)
#define FMA2(d, a, b) asm("fma.rn.f32x2 %0, %1, %2, %0;" : "+l"(d) : "l"(a), "l"(b))

// ---------------- device scratch (no allocs allowed) ----------------
__device__ float d_ha0[BATCH * AH];
__device__ float d_g[BATCH * ZH];
__device__ float d_zwb[BATCH * ZH];
__device__ float d_u[BATCH * ZDIM];
__device__ float d_simmat[BATCH * LDSIM];
__device__ float d_rowlog[BATCH];
__device__ int   d_rowcnt[BATCH];

// ---------------- ha0 = relu(actions @ Wa + ba) ----------------
__global__ void k_ha0(const float* __restrict__ actions,
                      const float* __restrict__ Wa,
                      const float* __restrict__ ba,
                      float* __restrict__ ha0) {
    int b = blockIdx.x;
    int h = threadIdx.x;   // 64 threads
    float s = ba[h];
#pragma unroll
    for (int a = 0; a < ADIM; a++)
        s += actions[b * ADIM + a] * Wa[a * AH + h];
    ha0[b * AH + h] = fmaxf(s, 0.f);
}

// ---------------- fp32 GEMM, 64x64 tile, 4x4 micro, double-buffered, f32x2 FMA ---------
// C[M,N] = A[M,K] @ (TRANSB ? B^T : B) (+ bias if BIAS)
// SPLIT: blocks with n0 >= nsplit use (Bsplit, Csplit, ldcs) with n0 -= nsplit.
template <bool TRANSB, bool BIAS, bool SPLIT>
__global__ void gemm_f2(const float* __restrict__ A,
                        const float* __restrict__ B,
                        const float* __restrict__ Bsplit,
                        const float* __restrict__ bias,
                        float* __restrict__ C,
                        float* __restrict__ Csplit,
                        int K, int lda, int ldb, int ldc, int ldcs, int nsplit) {
    // A tile stored as duplicated pairs {a,a} so LDS yields packed f32x2 operands.
    __shared__ float2 As[2][16][64];   // [stage][k][m]  16 KB
    __shared__ float  Bs[2][16][64];   // [stage][k][n]   8 KB

    const int tid = threadIdx.x;          // 256 threads
    const int tx = tid & 15;              // n micro
    const int ty = tid >> 4;              // m micro
    const int m0 = blockIdx.y * 64;
    int n0 = blockIdx.x * 64;

    const float* Bp = B;
    float* Cout = C;
    int ldco = ldc;
    if (SPLIT && n0 >= nsplit) { Bp = Bsplit; Cout = Csplit; ldco = ldcs; n0 -= nsplit; }

    // A loader: 64 rows x 16 k as float4
    const int ar = tid >> 2;              // 0..63
    const int ac = (tid & 3) * 4;         // 0,4,8,12
    // B loader (NN): 16 k x 64 n as float4
    const int br = tid >> 4;              // 0..15
    const int bc = (tid & 15) * 4;        // 0..60

    const float* Aptr = A + (size_t)(m0 + ar) * lda + ac;
    const float* Bptr = TRANSB ? Bp + (size_t)(n0 + ar) * ldb + ac
                               : Bp + (size_t)br * ldb + n0 + bc;

    ull acc[4][2];
#pragma unroll
    for (int i = 0; i < 4; i++) { acc[i][0] = 0ull; acc[i][1] = 0ull; }

    float4 a_reg = *(const float4*)Aptr;
    float4 b_reg = *(const float4*)Bptr;

    // stage tile 0
    As[0][ac + 0][ar] = make_float2(a_reg.x, a_reg.x);
    As[0][ac + 1][ar] = make_float2(a_reg.y, a_reg.y);
    As[0][ac + 2][ar] = make_float2(a_reg.z, a_reg.z);
    As[0][ac + 3][ar] = make_float2(a_reg.w, a_reg.w);
    if (TRANSB) {
        Bs[0][ac + 0][ar] = b_reg.x; Bs[0][ac + 1][ar] = b_reg.y;
        Bs[0][ac + 2][ar] = b_reg.z; Bs[0][ac + 3][ar] = b_reg.w;
    } else {
        Bs[0][br][bc + 0] = b_reg.x; Bs[0][br][bc + 1] = b_reg.y;
        Bs[0][br][bc + 2] = b_reg.z; Bs[0][br][bc + 3] = b_reg.w;
    }
    __syncthreads();

    const int T = K / 16;
    for (int t = 0; t < T; t++) {
        const int s = t & 1;
        // prefetch next tile into registers (hidden under compute)
        if (t + 1 < T) {
            a_reg = *(const float4*)(Aptr + (t + 1) * 16);
            b_reg = TRANSB ? *(const float4*)(Bptr + (t + 1) * 16)
                           : *(const float4*)(Bptr + (size_t)(t + 1) * 16 * ldb);
        }
#pragma unroll
        for (int kk = 0; kk < 16; kk++) {
            ulonglong2 ra01 = *(const ulonglong2*)&As[s][kk][ty * 4];
            ulonglong2 ra23 = *(const ulonglong2*)&As[s][kk][ty * 4 + 2];
            ulonglong2 rb   = *(const ulonglong2*)&Bs[s][kk][tx * 4];
            FMA2(acc[0][0], ra01.x, rb.x); FMA2(acc[0][1], ra01.x, rb.y);
            FMA2(acc[1][0], ra01.y, rb.x); FMA2(acc[1][1], ra01.y, rb.y);
            FMA2(acc[2][0], ra23.x, rb.x); FMA2(acc[2][1], ra23.x, rb.y);
            FMA2(acc[3][0], ra23.y, rb.x); FMA2(acc[3][1], ra23.y, rb.y);
        }
        if (t + 1 < T) {
            const int ns = (t + 1) & 1;
            As[ns][ac + 0][ar] = make_float2(a_reg.x, a_reg.x);
            As[ns][ac + 1][ar] = make_float2(a_reg.y, a_reg.y);
            As[ns][ac + 2][ar] = make_float2(a_reg.z, a_reg.z);
            As[ns][ac + 3][ar] = make_float2(a_reg.w, a_reg.w);
            if (TRANSB) {
                Bs[ns][ac + 0][ar] = b_reg.x; Bs[ns][ac + 1][ar] = b_reg.y;
                Bs[ns][ac + 2][ar] = b_reg.z; Bs[ns][ac + 3][ar] = b_reg.w;
            } else {
                Bs[ns][br][bc + 0] = b_reg.x; Bs[ns][br][bc + 1] = b_reg.y;
                Bs[ns][br][bc + 2] = b_reg.z; Bs[ns][br][bc + 3] = b_reg.w;
            }
        }
        __syncthreads();
    }

#pragma unroll
    for (int i = 0; i < 4; i++) {
        float2 v0 = *(float2*)&acc[i][0];
        float2 v1 = *(float2*)&acc[i][1];
        float4 o = make_float4(v0.x, v0.y, v1.x, v1.y);
        int n = n0 + tx * 4;
        if (BIAS) {
            o.x += bias[n + 0]; o.y += bias[n + 1];
            o.z += bias[n + 2]; o.w += bias[n + 3];
        }
        *(float4*)&Cout[(size_t)(m0 + ty * 4 + i) * ldco + n] = o;
    }
}

// ---------------- neg_sim: 8 batch rows per block, float4 ----------------
// neg_sim[b,i] = dot(z[b]+b2, z_next[b]) + sum_k relu(zwb[b,k] + g[(b+i)%B,k]) * u[b,k]
#define NEG_BT 8
__global__ void k_neg(const float* __restrict__ z, const float* __restrict__ zn,
                      const float* __restrict__ b2,
                      const float* __restrict__ zwb, const float* __restrict__ g,
                      const float* __restrict__ u, float* __restrict__ simmat) {
    int b0 = blockIdx.x * NEG_BT;
    int tid = threadIdx.x;   // 256
    int wid = tid >> 5, lane = tid & 31;

    __shared__ float4 s_zwb[NEG_BT][128];
    __shared__ float4 s_u[NEG_BT][128];
    __shared__ float  s_base[NEG_BT];

    for (int idx = tid; idx < NEG_BT * 128; idx += 256) {
        int bb = idx >> 7, k4 = idx & 127;
        s_zwb[bb][k4] = ((const float4*)zwb)[(size_t)(b0 + bb) * 128 + k4];
        s_u[bb][k4]   = ((const float4*)u)[(size_t)(b0 + bb) * 128 + k4];
    }
    // base term: one warp per b
    {
        int b = b0 + wid;
        float t = 0.f;
        for (int k = lane; k < ZDIM; k += 32) {
            float znv = zn[b * ZDIM + k];
            t += (z[b * ZDIM + k] + b2[k]) * znv;
        }
#pragma unroll
        for (int o = 16; o; o >>= 1) t += __shfl_xor_sync(0xffffffffu, t, o);
        if (lane == 0) s_base[wid] = t;
    }
    __syncthreads();

    for (int p = wid; p < NEG_BT * (NNEG - 1); p += 8) {
        int bb = p / (NNEG - 1);
        int i  = p - bb * (NNEG - 1) + 1;
        int b  = b0 + bb;
        int row = (b + i) & (BATCH - 1);
        const float4* gr = (const float4*)(g + (size_t)row * ZH);
        float acc = 0.f;
#pragma unroll
        for (int it = 0; it < 4; it++) {
            float4 gv = gr[lane + 32 * it];
            float4 zv = s_zwb[bb][lane + 32 * it];
            float4 uv = s_u[bb][lane + 32 * it];
            acc += fmaxf(zv.x + gv.x, 0.f) * uv.x;
            acc += fmaxf(zv.y + gv.y, 0.f) * uv.y;
            acc += fmaxf(zv.z + gv.z, 0.f) * uv.z;
            acc += fmaxf(zv.w + gv.w, 0.f) * uv.w;
        }
#pragma unroll
        for (int o = 16; o; o >>= 1) acc += __shfl_xor_sync(0xffffffffu, acc, o);
        if (lane == 0)
            simmat[(size_t)b * LDSIM + (BATCH - 1) + i] = s_base[bb] + acc;
    }
}

// ---------------- per-row log-softmax diag + rank count ----------------
__global__ void k_row(const float* __restrict__ simmat,
                      float* __restrict__ rowlog, int* __restrict__ rowcnt) {
    int b = blockIdx.x;
    int tid = threadIdx.x;   // 256
    const float* row = simmat + (size_t)b * LDSIM;
    float s = row[b];

    __shared__ float smx[8];
    __shared__ int   scn[8];
    __shared__ float ssm[8];
    __shared__ float s_mx;

    float mx = -INFINITY;
    int cnt = 0;
    for (int j = tid; j < NCOLS; j += 256) {
        float v = row[j];
        mx = fmaxf(mx, v);
        cnt += (v > s) || (v == s && j < b);
    }
#pragma unroll
    for (int o = 16; o; o >>= 1) {
        mx = fmaxf(mx, __shfl_xor_sync(0xffffffffu, mx, o));
        cnt += __shfl_xor_sync(0xffffffffu, cnt, o);
    }
    if ((tid & 31) == 0) { smx[tid >> 5] = mx; scn[tid >> 5] = cnt; }
    __syncthreads();
    if (tid == 0) {
        float m = smx[0]; int c = scn[0];
#pragma unroll
        for (int w = 1; w < 8; w++) { m = fmaxf(m, smx[w]); c += scn[w]; }
        s_mx = m;
        rowcnt[b] = c;
    }
    __syncthreads();
    float m = s_mx;

    float se = 0.f;
    for (int j = tid; j < NCOLS; j += 256)
        se += __expf((row[j] - m) * 10.f);
#pragma unroll
    for (int o = 16; o; o >>= 1) se += __shfl_xor_sync(0xffffffffu, se, o);
    if ((tid & 31) == 0) ssm[tid >> 5] = se;
    __syncthreads();
    if (tid == 0) {
        float t = 0.f;
#pragma unroll
        for (int w = 0; w < 8; w++) t += ssm[w];
        rowlog[b] = (s - m) * 10.f - logf(t);
    }
}

// ---------------- final reduction over rows ----------------
__global__ void k_final(const float* __restrict__ rowlog,
                        const int* __restrict__ rowcnt,
                        float* __restrict__ out) {
    int tid = threadIdx.x;  // 1024
    float lg = rowlog[tid];
    int c = rowcnt[tid];
    float a1 = (c < 1) ? 1.f : 0.f;
    float a3 = (c < 3) ? 1.f : 0.f;
    float a10 = (c < 10) ? 1.f : 0.f;

    __shared__ float s0[32], s1[32], s2[32], s3[32];
#pragma unroll
    for (int o = 16; o; o >>= 1) {
        lg  += __shfl_xor_sync(0xffffffffu, lg, o);
        a1  += __shfl_xor_sync(0xffffffffu, a1, o);
        a3  += __shfl_xor_sync(0xffffffffu, a3, o);
        a10 += __shfl_xor_sync(0xffffffffu, a10, o);
    }
    int wid = tid >> 5, lane = tid & 31;
    if (lane == 0) { s0[wid] = lg; s1[wid] = a1; s2[wid] = a3; s3[wid] = a10; }
    __syncthreads();
    if (wid == 0) {
        float v0 = s0[lane], v1 = s1[lane], v2 = s2[lane], v3 = s3[lane];
#pragma unroll
        for (int o = 16; o; o >>= 1) {
            v0 += __shfl_xor_sync(0xffffffffu, v0, o);
            v1 += __shfl_xor_sync(0xffffffffu, v1, o);
            v2 += __shfl_xor_sync(0xffffffffu, v2, o);
            v3 += __shfl_xor_sync(0xffffffffu, v3, o);
        }
        if (lane == 0) {
            out[0] = -v0 / (float)BATCH;
            out[1] = v1 / (float)BATCH;
            out[2] = v2 / (float)BATCH;
            out[3] = v3 / (float)BATCH;
        }
    }
}

// ---------------- launch ----------------
extern "C" void kernel_launch(void* const* d_in, const int* in_sizes, int n_in,
                              void* d_out, int out_size) {
    const float* z          = (const float*)d_in[0];
    const float* z_next     = (const float*)d_in[1];
    const float* z_next_hat = (const float*)d_in[2];
    const float* actions    = (const float*)d_in[3];
    const float* Wa         = (const float*)d_in[4];
    const float* ba         = (const float*)d_in[5];
    const float* W1         = (const float*)d_in[6];
    const float* b1         = (const float*)d_in[7];
    const float* W2         = (const float*)d_in[8];
    const float* b2         = (const float*)d_in[9];
    float* out = (float*)d_out;

    float *ha0, *g, *zwb, *u, *simmat, *rowlog;
    int* rowcnt;
    cudaGetSymbolAddress((void**)&ha0, d_ha0);
    cudaGetSymbolAddress((void**)&g, d_g);
    cudaGetSymbolAddress((void**)&zwb, d_zwb);
    cudaGetSymbolAddress((void**)&u, d_u);
    cudaGetSymbolAddress((void**)&simmat, d_simmat);
    cudaGetSymbolAddress((void**)&rowlog, d_rowlog);
    cudaGetSymbolAddress((void**)&rowcnt, d_rowcnt);

    // 1. ha0 = relu(actions @ Wa + ba)           [1024, 64]
    k_ha0<<<BATCH, AH>>>(actions, Wa, ba, ha0);

    // 2. g = ha0 @ W1[512:576, :]                [1024, 512]  (NN, K=64)
    gemm_f2<false, false, false><<<dim3(ZH / 64, BATCH / 64), 256>>>(
        ha0, W1 + (size_t)ZDIM * ZH, nullptr, nullptr, g, nullptr,
        AH, AH, ZH, ZH, 0, 0);

    // 3. zwb = z @ W1[0:512, :] + b1             [1024, 512]  (NN, K=512)
    gemm_f2<false, true, false><<<dim3(ZH / 64, BATCH / 64), 256>>>(
        z, W1, nullptr, b1, zwb, nullptr,
        ZDIM, ZDIM, ZH, ZH, 0, 0);

    // 4+5 fused: sim = z_next @ z_next_hat^T -> simmat[:,0:1024]
    //            u   = z_next @ W2^T           -> u[1024,512]
    gemm_f2<true, false, true><<<dim3((BATCH + ZDIM) / 64, BATCH / 64), 256>>>(
        z_next, z_next_hat, W2, nullptr, simmat, u,
        ZDIM, ZDIM, ZDIM, LDSIM, ZDIM, BATCH);

    // 6. neg_sim columns 1024..1122
    k_neg<<<BATCH / NEG_BT, 256>>>(z, z_next, b2, zwb, g, u, simmat);

    // 7. per-row log-softmax diagonal + rank counts
    k_row<<<BATCH, 256>>>(simmat, rowlog, rowcnt);

    // 8. final scalar outputs
    k_final<<<1, 1024>>>(rowlog, rowcnt, out);
}

// round 4
// speedup vs baseline: 1.1737x; 1.1737x over previous
#include <cuda_runtime.h>
#include <cuda_bf16.h>
#include <math.h>

// Problem constants
#define BATCH 1024
#define ZDIM  512
#define ADIM  8
#define AH    64
#define ZH    512
#define NNEG  100           // shifts 1..99 -> 99 extra columns
#define NCOLS 1123          // 1024 + 99
#define LDSIM 1152          // padded row stride for sim_mat

typedef unsigned long long ull;

// packed dual-FMA: d = a * b + d  (two fp32 lanes per instruction)
#define FMA2(d, a, b) asm("fma.rn.f32x2 %0, %1, %2, %0;" : "+l"(d) : "l"(a), "l"(b))

__device__ __forceinline__ ull dupf(float x) {
    float2 t = make_float2(x, x);
    return *(ull*)&t;
}

// ---------------- device scratch (no allocs allowed) ----------------
__device__ float d_ha0[BATCH * AH];
__device__ float d_g[BATCH * ZH];
__device__ float d_zwb[BATCH * ZH];
__device__ float d_u[BATCH * ZDIM];
__device__ float d_simmat[BATCH * LDSIM];
__device__ float d_rowlog[BATCH];
__device__ int   d_rowcnt[BATCH];

// ---------------- ha0 = relu(actions @ Wa + ba) ----------------
__global__ void k_ha0(const float* __restrict__ actions,
                      const float* __restrict__ Wa,
                      const float* __restrict__ ba,
                      float* __restrict__ ha0) {
    int b = blockIdx.x;
    int h = threadIdx.x;   // 64 threads
    float s = ba[h];
#pragma unroll
    for (int a = 0; a < ADIM; a++)
        s += actions[b * ADIM + a] * Wa[a * AH + h];
    ha0[b * AH + h] = fmaxf(s, 0.f);
}

// ---------------- mega GEMM: all three GEMMs, one launch -------------------
// CTA tile 64(M) x 128(N), BK=16, 128 threads, 8x8 microtile, f32x2 FMA.
// Segments by blockIdx.x:
//   [0,192):   fused  C = z_next @ {z_next_hat|W2}^T   (sim -> simmat, u)
//   [192,256): zwb    C = z @ W1[0:512] + b1
//   [256,320): g      C = ha0 @ W1[512:576]
#define PAD_A 68
#define PAD_B 132
#define N_FUSED 192
#define N_ZWB   64
#define N_G     64

__global__ void __launch_bounds__(128, 4)
k_gemms(const float* __restrict__ z, const float* __restrict__ z_next,
        const float* __restrict__ z_next_hat,
        const float* __restrict__ W1, const float* __restrict__ b1,
        const float* __restrict__ W2, const float* __restrict__ ha0,
        float* __restrict__ zwb, float* __restrict__ g,
        float* __restrict__ u, float* __restrict__ simmat) {
    __shared__ float As[2][16][PAD_A];   // [stage][k][m]
    __shared__ float Bs[2][16][PAD_B];   // [stage][k][n]

    const int tid = threadIdx.x;         // 128 threads
    const int tx = tid & 15;             // n micro (0..15)
    const int ty = tid >> 4;             // m micro (0..7)

    // segment dispatch
    const float* A; const float* B; const float* bias = nullptr;
    float* C; int lda, ldb, ldc, K, m0, n0; bool transb;
    int bid = blockIdx.x;
    if (bid < N_FUSED) {
        int nt = bid % 12, mt = bid / 12;
        m0 = mt * 64; A = z_next; lda = ZDIM; K = ZDIM; transb = true; ldb = ZDIM;
        if (nt < 8) { B = z_next_hat; C = simmat; ldc = LDSIM; n0 = nt * 128; }
        else        { B = W2;         C = u;      ldc = ZDIM;  n0 = (nt - 8) * 128; }
    } else if (bid < N_FUSED + N_ZWB) {
        int t = bid - N_FUSED;
        int nt = t & 3, mt = t >> 2;
        m0 = mt * 64; n0 = nt * 128;
        A = z; lda = ZDIM; K = ZDIM; transb = false;
        B = W1; ldb = ZH; bias = b1; C = zwb; ldc = ZH;
    } else {
        int t = bid - N_FUSED - N_ZWB;
        int nt = t & 3, mt = t >> 2;
        m0 = mt * 64; n0 = nt * 128;
        A = ha0; lda = AH; K = AH; transb = false;
        B = W1 + (size_t)ZDIM * ZH; ldb = ZH; C = g; ldc = ZH;
    }

    // ---- loader indices ----
    // A: 64 rows x 16 k -> 128 thr x 2 float4
    const int ar = tid >> 1;             // 0..63 (m)
    const int ac = (tid & 1) * 8;        // 0 or 8 (k)
    const float* Aptr = A + (size_t)(m0 + ar) * lda + ac;
    // B transb: each thread owns one n-row (tid), 16 k -> 4 float4
    const float* Bt = B + (size_t)(n0 + tid) * ldb;
    // B nn: 16 k-rows x 128 n -> kr=tid>>3 (0..15), nc=(tid&7)*16 -> 4 float4
    const int kr = tid >> 3;
    const int nc = (tid & 7) * 16;
    const float* Bn = B + (size_t)kr * ldb + n0 + nc;

    ull acc[4][8];
#pragma unroll
    for (int i = 0; i < 4; i++)
#pragma unroll
        for (int j = 0; j < 8; j++) acc[i][j] = 0ull;

    float4 a0, a1, b0, b1r, b2, b3;

    // ---- load tile 0 into regs ----
    a0 = *(const float4*)(Aptr);
    a1 = *(const float4*)(Aptr + 4);
    if (transb) {
        b0 = *(const float4*)(Bt + 0);  b1r = *(const float4*)(Bt + 4);
        b2 = *(const float4*)(Bt + 8);  b3  = *(const float4*)(Bt + 12);
    } else {
        b0 = *(const float4*)(Bn + 0);  b1r = *(const float4*)(Bn + 4);
        b2 = *(const float4*)(Bn + 8);  b3  = *(const float4*)(Bn + 12);
    }
    // stage 0
    {
        As[0][ac + 0][ar] = a0.x; As[0][ac + 1][ar] = a0.y;
        As[0][ac + 2][ar] = a0.z; As[0][ac + 3][ar] = a0.w;
        As[0][ac + 4][ar] = a1.x; As[0][ac + 5][ar] = a1.y;
        As[0][ac + 6][ar] = a1.z; As[0][ac + 7][ar] = a1.w;
        if (transb) {
            Bs[0][0][tid] = b0.x;  Bs[0][1][tid] = b0.y;
            Bs[0][2][tid] = b0.z;  Bs[0][3][tid] = b0.w;
            Bs[0][4][tid] = b1r.x; Bs[0][5][tid] = b1r.y;
            Bs[0][6][tid] = b1r.z; Bs[0][7][tid] = b1r.w;
            Bs[0][8][tid] = b2.x;  Bs[0][9][tid] = b2.y;
            Bs[0][10][tid] = b2.z; Bs[0][11][tid] = b2.w;
            Bs[0][12][tid] = b3.x; Bs[0][13][tid] = b3.y;
            Bs[0][14][tid] = b3.z; Bs[0][15][tid] = b3.w;
        } else {
            *(float4*)&Bs[0][kr][nc + 0]  = b0;
            *(float4*)&Bs[0][kr][nc + 4]  = b1r;
            *(float4*)&Bs[0][kr][nc + 8]  = b2;
            *(float4*)&Bs[0][kr][nc + 12] = b3;
        }
    }
    __syncthreads();

    const int T = K / 16;
    for (int t = 0; t < T; t++) {
        const int s = t & 1;
        if (t + 1 < T) {
            a0 = *(const float4*)(Aptr + (t + 1) * 16);
            a1 = *(const float4*)(Aptr + (t + 1) * 16 + 4);
            if (transb) {
                const float* p = Bt + (t + 1) * 16;
                b0 = *(const float4*)(p + 0);  b1r = *(const float4*)(p + 4);
                b2 = *(const float4*)(p + 8);  b3  = *(const float4*)(p + 12);
            } else {
                const float* p = Bn + (size_t)(t + 1) * 16 * ldb;
                b0 = *(const float4*)(p + 0);  b1r = *(const float4*)(p + 4);
                b2 = *(const float4*)(p + 8);  b3  = *(const float4*)(p + 12);
            }
        }
#pragma unroll
        for (int kk = 0; kk < 16; kk++) {
            // a-frag: 8 floats = 4 natural (m,m+1) pairs
            ulonglong2 ap0 = *(const ulonglong2*)&As[s][kk][ty * 8];
            ulonglong2 ap1 = *(const ulonglong2*)&As[s][kk][ty * 8 + 4];
            // b-frag: 8 floats
            float4 bv0 = *(const float4*)&Bs[s][kk][tx * 8];
            float4 bv1 = *(const float4*)&Bs[s][kk][tx * 8 + 4];
            ull bd[8];
            bd[0] = dupf(bv0.x); bd[1] = dupf(bv0.y);
            bd[2] = dupf(bv0.z); bd[3] = dupf(bv0.w);
            bd[4] = dupf(bv1.x); bd[5] = dupf(bv1.y);
            bd[6] = dupf(bv1.z); bd[7] = dupf(bv1.w);
#pragma unroll
            for (int j = 0; j < 8; j++) {
                FMA2(acc[0][j], ap0.x, bd[j]);
                FMA2(acc[1][j], ap0.y, bd[j]);
                FMA2(acc[2][j], ap1.x, bd[j]);
                FMA2(acc[3][j], ap1.y, bd[j]);
            }
        }
        if (t + 1 < T) {
            const int ns = (t + 1) & 1;
            As[ns][ac + 0][ar] = a0.x; As[ns][ac + 1][ar] = a0.y;
            As[ns][ac + 2][ar] = a0.z; As[ns][ac + 3][ar] = a0.w;
            As[ns][ac + 4][ar] = a1.x; As[ns][ac + 5][ar] = a1.y;
            As[ns][ac + 6][ar] = a1.z; As[ns][ac + 7][ar] = a1.w;
            if (transb) {
                Bs[ns][0][tid] = b0.x;  Bs[ns][1][tid] = b0.y;
                Bs[ns][2][tid] = b0.z;  Bs[ns][3][tid] = b0.w;
                Bs[ns][4][tid] = b1r.x; Bs[ns][5][tid] = b1r.y;
                Bs[ns][6][tid] = b1r.z; Bs[ns][7][tid] = b1r.w;
                Bs[ns][8][tid] = b2.x;  Bs[ns][9][tid] = b2.y;
                Bs[ns][10][tid] = b2.z; Bs[ns][11][tid] = b2.w;
                Bs[ns][12][tid] = b3.x; Bs[ns][13][tid] = b3.y;
                Bs[ns][14][tid] = b3.z; Bs[ns][15][tid] = b3.w;
            } else {
                *(float4*)&Bs[ns][kr][nc + 0]  = b0;
                *(float4*)&Bs[ns][kr][nc + 4]  = b1r;
                *(float4*)&Bs[ns][kr][nc + 8]  = b2;
                *(float4*)&Bs[ns][kr][nc + 12] = b3;
            }
        }
        __syncthreads();
    }

    // ---- epilogue: unpack, optional bias, write 8x8 as 2x float4 per row ----
    float bsv[8];
    if (bias) {
#pragma unroll
        for (int j = 0; j < 8; j++) bsv[j] = bias[n0 + tx * 8 + j];
    } else {
#pragma unroll
        for (int j = 0; j < 8; j++) bsv[j] = 0.f;
    }
#pragma unroll
    for (int i = 0; i < 8; i++) {
        float v[8];
#pragma unroll
        for (int j = 0; j < 8; j++) {
            float2 p = *(float2*)&acc[i >> 1][j];
            v[j] = ((i & 1) ? p.y : p.x) + bsv[j];
        }
        float* Crow = C + (size_t)(m0 + ty * 8 + i) * ldc + n0 + tx * 8;
        *(float4*)(Crow + 0) = make_float4(v[0], v[1], v[2], v[3]);
        *(float4*)(Crow + 4) = make_float4(v[4], v[5], v[6], v[7]);
    }
}

// ---------------- neg_sim: 8 batch rows per block, float4 ----------------
#define NEG_BT 8
__global__ void k_neg(const float* __restrict__ z, const float* __restrict__ zn,
                      const float* __restrict__ b2,
                      const float* __restrict__ zwb, const float* __restrict__ g,
                      const float* __restrict__ u, float* __restrict__ simmat) {
    int b0 = blockIdx.x * NEG_BT;
    int tid = threadIdx.x;   // 256
    int wid = tid >> 5, lane = tid & 31;

    __shared__ float4 s_zwb[NEG_BT][128];
    __shared__ float4 s_u[NEG_BT][128];
    __shared__ float  s_base[NEG_BT];

    for (int idx = tid; idx < NEG_BT * 128; idx += 256) {
        int bb = idx >> 7, k4 = idx & 127;
        s_zwb[bb][k4] = ((const float4*)zwb)[(size_t)(b0 + bb) * 128 + k4];
        s_u[bb][k4]   = ((const float4*)u)[(size_t)(b0 + bb) * 128 + k4];
    }
    {
        int b = b0 + wid;
        float t = 0.f;
        for (int k = lane; k < ZDIM; k += 32) {
            float znv = zn[b * ZDIM + k];
            t += (z[b * ZDIM + k] + b2[k]) * znv;
        }
#pragma unroll
        for (int o = 16; o; o >>= 1) t += __shfl_xor_sync(0xffffffffu, t, o);
        if (lane == 0) s_base[wid] = t;
    }
    __syncthreads();

    for (int p = wid; p < NEG_BT * (NNEG - 1); p += 8) {
        int bb = p / (NNEG - 1);
        int i  = p - bb * (NNEG - 1) + 1;
        int b  = b0 + bb;
        int row = (b + i) & (BATCH - 1);
        const float4* gr = (const float4*)(g + (size_t)row * ZH);
        float acc = 0.f;
#pragma unroll
        for (int it = 0; it < 4; it++) {
            float4 gv = gr[lane + 32 * it];
            float4 zv = s_zwb[bb][lane + 32 * it];
            float4 uv = s_u[bb][lane + 32 * it];
            acc += fmaxf(zv.x + gv.x, 0.f) * uv.x;
            acc += fmaxf(zv.y + gv.y, 0.f) * uv.y;
            acc += fmaxf(zv.z + gv.z, 0.f) * uv.z;
            acc += fmaxf(zv.w + gv.w, 0.f) * uv.w;
        }
#pragma unroll
        for (int o = 16; o; o >>= 1) acc += __shfl_xor_sync(0xffffffffu, acc, o);
        if (lane == 0)
            simmat[(size_t)b * LDSIM + (BATCH - 1) + i] = s_base[bb] + acc;
    }
}

// ---------------- per-row log-softmax diag + rank count ----------------
__global__ void k_row(const float* __restrict__ simmat,
                      float* __restrict__ rowlog, int* __restrict__ rowcnt) {
    int b = blockIdx.x;
    int tid = threadIdx.x;   // 256
    const float* row = simmat + (size_t)b * LDSIM;
    float s = row[b];

    __shared__ float smx[8];
    __shared__ int   scn[8];
    __shared__ float ssm[8];
    __shared__ float s_mx;

    float mx = -INFINITY;
    int cnt = 0;
    for (int j = tid; j < NCOLS; j += 256) {
        float v = row[j];
        mx = fmaxf(mx, v);
        cnt += (v > s) || (v == s && j < b);
    }
#pragma unroll
    for (int o = 16; o; o >>= 1) {
        mx = fmaxf(mx, __shfl_xor_sync(0xffffffffu, mx, o));
        cnt += __shfl_xor_sync(0xffffffffu, cnt, o);
    }
    if ((tid & 31) == 0) { smx[tid >> 5] = mx; scn[tid >> 5] = cnt; }
    __syncthreads();
    if (tid == 0) {
        float m = smx[0]; int c = scn[0];
#pragma unroll
        for (int w = 1; w < 8; w++) { m = fmaxf(m, smx[w]); c += scn[w]; }
        s_mx = m;
        rowcnt[b] = c;
    }
    __syncthreads();
    float m = s_mx;

    float se = 0.f;
    for (int j = tid; j < NCOLS; j += 256)
        se += __expf((row[j] - m) * 10.f);
#pragma unroll
    for (int o = 16; o; o >>= 1) se += __shfl_xor_sync(0xffffffffu, se, o);
    if ((tid & 31) == 0) ssm[tid >> 5] = se;
    __syncthreads();
    if (tid == 0) {
        float t = 0.f;
#pragma unroll
        for (int w = 0; w < 8; w++) t += ssm[w];
        rowlog[b] = (s - m) * 10.f - logf(t);
    }
}

// ---------------- final reduction over rows ----------------
__global__ void k_final(const float* __restrict__ rowlog,
                        const int* __restrict__ rowcnt,
                        float* __restrict__ out) {
    int tid = threadIdx.x;  // 1024
    float lg = rowlog[tid];
    int c = rowcnt[tid];
    float a1 = (c < 1) ? 1.f : 0.f;
    float a3 = (c < 3) ? 1.f : 0.f;
    float a10 = (c < 10) ? 1.f : 0.f;

    __shared__ float s0[32], s1[32], s2[32], s3[32];
#pragma unroll
    for (int o = 16; o; o >>= 1) {
        lg  += __shfl_xor_sync(0xffffffffu, lg, o);
        a1  += __shfl_xor_sync(0xffffffffu, a1, o);
        a3  += __shfl_xor_sync(0xffffffffu, a3, o);
        a10 += __shfl_xor_sync(0xffffffffu, a10, o);
    }
    int wid = tid >> 5, lane = tid & 31;
    if (lane == 0) { s0[wid] = lg; s1[wid] = a1; s2[wid] = a3; s3[wid] = a10; }
    __syncthreads();
    if (wid == 0) {
        float v0 = s0[lane], v1 = s1[lane], v2 = s2[lane], v3 = s3[lane];
#pragma unroll
        for (int o = 16; o; o >>= 1) {
            v0 += __shfl_xor_sync(0xffffffffu, v0, o);
            v1 += __shfl_xor_sync(0xffffffffu, v1, o);
            v2 += __shfl_xor_sync(0xffffffffu, v2, o);
            v3 += __shfl_xor_sync(0xffffffffu, v3, o);
        }
        if (lane == 0) {
            out[0] = -v0 / (float)BATCH;
            out[1] = v1 / (float)BATCH;
            out[2] = v2 / (float)BATCH;
            out[3] = v3 / (float)BATCH;
        }
    }
}

// ---------------- launch ----------------
extern "C" void kernel_launch(void* const* d_in, const int* in_sizes, int n_in,
                              void* d_out, int out_size) {
    const float* z          = (const float*)d_in[0];
    const float* z_next     = (const float*)d_in[1];
    const float* z_next_hat = (const float*)d_in[2];
    const float* actions    = (const float*)d_in[3];
    const float* Wa         = (const float*)d_in[4];
    const float* ba         = (const float*)d_in[5];
    const float* W1         = (const float*)d_in[6];
    const float* b1         = (const float*)d_in[7];
    const float* W2         = (const float*)d_in[8];
    const float* b2         = (const float*)d_in[9];
    float* out = (float*)d_out;

    float *ha0, *g, *zwb, *u, *simmat, *rowlog;
    int* rowcnt;
    cudaGetSymbolAddress((void**)&ha0, d_ha0);
    cudaGetSymbolAddress((void**)&g, d_g);
    cudaGetSymbolAddress((void**)&zwb, d_zwb);
    cudaGetSymbolAddress((void**)&u, d_u);
    cudaGetSymbolAddress((void**)&simmat, d_simmat);
    cudaGetSymbolAddress((void**)&rowlog, d_rowlog);
    cudaGetSymbolAddress((void**)&rowcnt, d_rowcnt);

    // 1. ha0 = relu(actions @ Wa + ba)           [1024, 64]
    k_ha0<<<BATCH, AH>>>(actions, Wa, ba, ha0);

    // 2. all GEMMs in one launch: sim+u (fused), zwb, g
    k_gemms<<<N_FUSED + N_ZWB + N_G, 128>>>(
        z, z_next, z_next_hat, W1, b1, W2, ha0, zwb, g, u, simmat);

    // 3. neg_sim columns 1024..1122
    k_neg<<<BATCH / NEG_BT, 256>>>(z, z_next, b2, zwb, g, u, simmat);

    // 4. per-row log-softmax diagonal + rank counts
    k_row<<<BATCH, 256>>>(simmat, rowlog, rowcnt);

    // 5. final scalar outputs
    k_final<<<1, 1024>>>(rowlog, rowcnt, out);
}

// round 6
// speedup vs baseline: 1.6092x; 1.3710x over previous
#include <cuda_runtime.h>
#include <cuda_bf16.h>
#include <math.h>
#include <stdint.h>

// Problem constants
#define BATCH 1024
#define ZDIM  512
#define ADIM  8
#define AH    64
#define ZH    512
#define NNEG  100
#define NCOLS 1123
#define LDSIM 1152

// split-bf16 stacked K dims
#define KP    1536          // 3*512
#define KPG   192           // 3*64

// ---------------- device scratch ----------------
__device__ float d_g[BATCH * ZH];
__device__ float d_zwb[BATCH * ZH];
__device__ float d_u[BATCH * ZDIM];
__device__ float d_simmat[BATCH * LDSIM];
__device__ float d_rowlog[BATCH];
__device__ int   d_rowcnt[BATCH];

__device__ __nv_bfloat16 d_Af[BATCH * KP];     // z_next'  [Ah|Ah|Al]
__device__ __nv_bfloat16 d_Az[BATCH * KP];     // z'
__device__ __nv_bfloat16 d_Ag[BATCH * KPG];    // ha0'
__device__ __nv_bfloat16 d_Bf[1536 * KP];      // rows 0:1024 znh', 1024:1536 W2'  [Bh|Bl|Bh]
__device__ __nv_bfloat16 d_Bw1[512 * KP];      // W1[0:512]^T'
__device__ __nv_bfloat16 d_Bg[512 * KPG];      // W1[512:576]^T'

// ---------------- ha0 + split -> Ag ----------------
__global__ void k_ha0(const float* __restrict__ actions,
                      const float* __restrict__ Wa,
                      const float* __restrict__ ba,
                      __nv_bfloat16* __restrict__ Ag) {
    int b = blockIdx.x;
    int h = threadIdx.x;   // 64
    float s = ba[h];
#pragma unroll
    for (int a = 0; a < ADIM; a++)
        s += actions[b * ADIM + a] * Wa[a * AH + h];
    s = fmaxf(s, 0.f);
    __nv_bfloat16 hi = __float2bfloat16(s);
    __nv_bfloat16 lo = __float2bfloat16(s - __bfloat162float(hi));
    __nv_bfloat16* r = Ag + (size_t)b * KPG;
    r[h] = hi; r[64 + h] = hi; r[128 + h] = lo;   // A pattern [h|h|l]
}

// ---------------- conversions: fp32 -> split-bf16 stacked ----------------
__global__ void k_conv(const float* __restrict__ zn, const float* __restrict__ z,
                       const float* __restrict__ znh, const float* __restrict__ W2,
                       const float* __restrict__ W1,
                       __nv_bfloat16* __restrict__ Af, __nv_bfloat16* __restrict__ Az,
                       __nv_bfloat16* __restrict__ Bf, __nv_bfloat16* __restrict__ Bw1,
                       __nv_bfloat16* __restrict__ Bg) {
    int bid = blockIdx.x, tid = threadIdx.x;
    float v; __nv_bfloat16* r; int k;
    if (bid < 2048) {                 // Af <- z_next (A pattern)
        int e = bid * 256 + tid; int m = e >> 9; k = e & 511;
        v = zn[e]; r = Af + (size_t)m * KP;
        __nv_bfloat16 h = __float2bfloat16(v), l = __float2bfloat16(v - __bfloat162float(h));
        r[k] = h; r[512 + k] = h; r[1024 + k] = l; return;
    } else if (bid < 4096) {          // Az <- z (A pattern)
        int e = (bid - 2048) * 256 + tid; int m = e >> 9; k = e & 511;
        v = z[e]; r = Az + (size_t)m * KP;
        __nv_bfloat16 h = __float2bfloat16(v), l = __float2bfloat16(v - __bfloat162float(h));
        r[k] = h; r[512 + k] = h; r[1024 + k] = l; return;
    } else if (bid < 6144) {          // Bf rows 0:1024 <- z_next_hat (B pattern)
        int e = (bid - 4096) * 256 + tid; int m = e >> 9; k = e & 511;
        v = znh[e]; r = Bf + (size_t)m * KP;
    } else if (bid < 7168) {          // Bf rows 1024:1536 <- W2 (B pattern)
        int e = (bid - 6144) * 256 + tid; int n = e >> 9; k = e & 511;
        v = W2[e]; r = Bf + (size_t)(1024 + n) * KP;
    } else if (bid < 8192) {          // Bw1 <- W1[0:512]^T (B pattern)
        int e = (bid - 7168) * 256 + tid; int n = e >> 9; k = e & 511;
        v = W1[(size_t)k * ZH + n]; r = Bw1 + (size_t)n * KP;
    } else {                          // Bg <- W1[512:576]^T (B pattern, blocks of 64)
        int e = (bid - 8192) * 256 + tid; int n = e >> 6; k = e & 63;
        v = W1[(size_t)(512 + k) * ZH + n];
        __nv_bfloat16 h = __float2bfloat16(v), l = __float2bfloat16(v - __bfloat162float(h));
        r = Bg + (size_t)n * KPG;
        r[k] = h; r[64 + k] = l; r[128 + k] = h; return;
    }
    __nv_bfloat16 h = __float2bfloat16(v), l = __float2bfloat16(v - __bfloat162float(h));
    r[k] = h; r[512 + k] = l; r[1024 + k] = h;    // B pattern [h|l|h]
}

// ---------------- HMMA GEMM: C[M,N] = A[M,K'] @ B[N,K']^T ------------------
// CTA 128x128, 8 warps (2M x 4N), warp tile 64x32, K-chunk 32, cp.async 2-stage.
// Segments by blockIdx.x:
//   [0,96):    fused  A=Af, B=Bf,  T=48 -> simmat (nt<8) / u (nt>=8)
//   [96,128):  zwb    A=Az, B=Bw1, T=48, bias=b1
//   [128,160): g      A=Ag, B=Bg,  T=6
#define SM_PITCH 40

__device__ __forceinline__ void mma16816(float* d, const uint32_t* a, const uint32_t* b) {
    asm volatile(
        "mma.sync.aligned.m16n8k16.row.col.f32.bf16.bf16.f32 "
        "{%0,%1,%2,%3}, {%4,%5,%6,%7}, {%8,%9}, {%0,%1,%2,%3};"
        : "+f"(d[0]), "+f"(d[1]), "+f"(d[2]), "+f"(d[3])
        : "r"(a[0]), "r"(a[1]), "r"(a[2]), "r"(a[3]), "r"(b[0]), "r"(b[1]));
}
__device__ __forceinline__ void cpa16(const void* s, const void* gp) {
    uint32_t sa;
    asm("{ .reg .u64 t; cvta.to.shared.u64 t, %1; cvt.u32.u64 %0, t; }" : "=r"(sa) : "l"(s));
    asm volatile("cp.async.cg.shared.global [%0], [%1], 16;\n" :: "r"(sa), "l"(gp));
}

__global__ void __launch_bounds__(256, 1)
k_mma(const __nv_bfloat16* __restrict__ Af, const __nv_bfloat16* __restrict__ Az,
      const __nv_bfloat16* __restrict__ Ag, const __nv_bfloat16* __restrict__ Bf,
      const __nv_bfloat16* __restrict__ Bw1, const __nv_bfloat16* __restrict__ Bg,
      const float* __restrict__ b1,
      float* __restrict__ zwb, float* __restrict__ g,
      float* __restrict__ u, float* __restrict__ simmat) {
    __shared__ __align__(16) __nv_bfloat16 As[2][128][SM_PITCH];
    __shared__ __align__(16) __nv_bfloat16 Bs[2][128][SM_PITCH];

    const int tid = threadIdx.x;          // 256
    const int lane = tid & 31, warp = tid >> 5;
    const int grp = lane >> 2, qid = lane & 3;
    const int wm = warp >> 2, wn = warp & 3;   // 2 x 4 warp grid

    // ---- segment dispatch ----
    const __nv_bfloat16 *Aseg, *Bseg;
    float* Cseg; const float* bias = nullptr;
    int ldk, T, m0, ldc, ccol0;
    {
        int bid = blockIdx.x;
        if (bid < 96) {
            int mt = bid / 12, nt = bid % 12;
            m0 = mt * 128; Aseg = Af; ldk = KP; T = 48;
            Bseg = Bf + (size_t)nt * 128 * KP;
            if (nt < 8) { Cseg = simmat; ldc = LDSIM; ccol0 = nt * 128; }
            else        { Cseg = u;      ldc = ZDIM;  ccol0 = (nt - 8) * 128; }
        } else if (bid < 128) {
            int t = bid - 96; int mt = t >> 2, nt = t & 3;
            m0 = mt * 128; Aseg = Az; ldk = KP; T = 48;
            Bseg = Bw1 + (size_t)nt * 128 * KP;
            Cseg = zwb; ldc = ZH; ccol0 = nt * 128; bias = b1;
        } else {
            int t = bid - 128; int mt = t >> 2, nt = t & 3;
            m0 = mt * 128; Aseg = Ag; ldk = KPG; T = 6;
            Bseg = Bg + (size_t)nt * 128 * KPG;
            Cseg = g; ldc = ZH; ccol0 = nt * 128;
        }
    }

    float acc[4][4][4];
#pragma unroll
    for (int i = 0; i < 4; i++)
#pragma unroll
        for (int j = 0; j < 4; j++)
#pragma unroll
            for (int q = 0; q < 4; q++) acc[i][j][q] = 0.f;

    // ---- chunk loader: 128 rows x 32 k for A and B, 16B per cp.async ----
    auto load_chunk = [&](int chunk, int st) {
#pragma unroll
        for (int it = 0; it < 2; it++) {
            int idx = it * 256 + tid;          // 0..511
            int row = idx >> 2, seg = (idx & 3) * 8;
            cpa16(&As[st][row][seg], Aseg + (size_t)(m0 + row) * ldk + chunk * 32 + seg);
        }
#pragma unroll
        for (int it = 0; it < 2; it++) {
            int idx = it * 256 + tid;
            int row = idx >> 2, seg = (idx & 3) * 8;
            cpa16(&Bs[st][row][seg], Bseg + (size_t)row * ldk + chunk * 32 + seg);
        }
        asm volatile("cp.async.commit_group;\n" ::: "memory");
    };

    load_chunk(0, 0);

    for (int t = 0; t < T; t++) {
        const int s = t & 1;
        if (t + 1 < T) load_chunk(t + 1, 1 - s);
        if (t + 1 < T) asm volatile("cp.async.wait_group 1;\n" ::: "memory");
        else           asm volatile("cp.async.wait_group 0;\n" ::: "memory");
        __syncthreads();

#pragma unroll
        for (int ks = 0; ks < 2; ks++) {
            const int kofs = ks * 16 + qid * 2;
            uint32_t afr[4][4], bfr[4][2];
#pragma unroll
            for (int mi = 0; mi < 4; mi++) {
                int r0 = wm * 64 + mi * 16 + grp;
                afr[mi][0] = *(const uint32_t*)&As[s][r0][kofs];
                afr[mi][1] = *(const uint32_t*)&As[s][r0 + 8][kofs];
                afr[mi][2] = *(const uint32_t*)&As[s][r0][kofs + 8];
                afr[mi][3] = *(const uint32_t*)&As[s][r0 + 8][kofs + 8];
            }
#pragma unroll
            for (int ni = 0; ni < 4; ni++) {
                int nr = wn * 32 + ni * 8 + grp;
                bfr[ni][0] = *(const uint32_t*)&Bs[s][nr][kofs];
                bfr[ni][1] = *(const uint32_t*)&Bs[s][nr][kofs + 8];
            }
#pragma unroll
            for (int mi = 0; mi < 4; mi++)
#pragma unroll
                for (int ni = 0; ni < 4; ni++)
                    mma16816(acc[mi][ni], afr[mi], bfr[ni]);
        }
        __syncthreads();
    }

    // ---- epilogue ----
#pragma unroll
    for (int mi = 0; mi < 4; mi++) {
        int m = m0 + wm * 64 + mi * 16 + grp;
#pragma unroll
        for (int ni = 0; ni < 4; ni++) {
            int n = ccol0 + wn * 32 + ni * 8 + qid * 2;
            float bx = 0.f, by = 0.f;
            if (bias) { bx = bias[n]; by = bias[n + 1]; }
            *(float2*)&Cseg[(size_t)m * ldc + n] =
                make_float2(acc[mi][ni][0] + bx, acc[mi][ni][1] + by);
            *(float2*)&Cseg[(size_t)(m + 8) * ldc + n] =
                make_float2(acc[mi][ni][2] + bx, acc[mi][ni][3] + by);
        }
    }
}

// ---------------- neg_sim ----------------
#define NEG_BT 8
__global__ void k_neg(const float* __restrict__ z, const float* __restrict__ zn,
                      const float* __restrict__ b2,
                      const float* __restrict__ zwb, const float* __restrict__ g,
                      const float* __restrict__ u, float* __restrict__ simmat) {
    int b0 = blockIdx.x * NEG_BT;
    int tid = threadIdx.x;   // 256
    int wid = tid >> 5, lane = tid & 31;

    __shared__ float4 s_zwb[NEG_BT][128];
    __shared__ float4 s_u[NEG_BT][128];
    __shared__ float  s_base[NEG_BT];

    for (int idx = tid; idx < NEG_BT * 128; idx += 256) {
        int bb = idx >> 7, k4 = idx & 127;
        s_zwb[bb][k4] = ((const float4*)zwb)[(size_t)(b0 + bb) * 128 + k4];
        s_u[bb][k4]   = ((const float4*)u)[(size_t)(b0 + bb) * 128 + k4];
    }
    {
        int b = b0 + wid;
        float t = 0.f;
        for (int k = lane; k < ZDIM; k += 32) {
            float znv = zn[b * ZDIM + k];
            t += (z[b * ZDIM + k] + b2[k]) * znv;
        }
#pragma unroll
        for (int o = 16; o; o >>= 1) t += __shfl_xor_sync(0xffffffffu, t, o);
        if (lane == 0) s_base[wid] = t;
    }
    __syncthreads();

    for (int p = wid; p < NEG_BT * (NNEG - 1); p += 8) {
        int bb = p / (NNEG - 1);
        int i  = p - bb * (NNEG - 1) + 1;
        int b  = b0 + bb;
        int row = (b + i) & (BATCH - 1);
        const float4* gr = (const float4*)(g + (size_t)row * ZH);
        float acc = 0.f;
#pragma unroll
        for (int it = 0; it < 4; it++) {
            float4 gv = gr[lane + 32 * it];
            float4 zv = s_zwb[bb][lane + 32 * it];
            float4 uv = s_u[bb][lane + 32 * it];
            acc += fmaxf(zv.x + gv.x, 0.f) * uv.x;
            acc += fmaxf(zv.y + gv.y, 0.f) * uv.y;
            acc += fmaxf(zv.z + gv.z, 0.f) * uv.z;
            acc += fmaxf(zv.w + gv.w, 0.f) * uv.w;
        }
#pragma unroll
        for (int o = 16; o; o >>= 1) acc += __shfl_xor_sync(0xffffffffu, acc, o);
        if (lane == 0)
            simmat[(size_t)b * LDSIM + (BATCH - 1) + i] = s_base[bb] + acc;
    }
}

// ---------------- per-row log-softmax diag + rank count ----------------
__global__ void k_row(const float* __restrict__ simmat,
                      float* __restrict__ rowlog, int* __restrict__ rowcnt) {
    int b = blockIdx.x;
    int tid = threadIdx.x;   // 256
    const float* row = simmat + (size_t)b * LDSIM;
    float s = row[b];

    __shared__ float smx[8];
    __shared__ int   scn[8];
    __shared__ float ssm[8];
    __shared__ float s_mx;

    float mx = -INFINITY;
    int cnt = 0;
    for (int j = tid; j < NCOLS; j += 256) {
        float v = row[j];
        mx = fmaxf(mx, v);
        cnt += (v > s) || (v == s && j < b);
    }
#pragma unroll
    for (int o = 16; o; o >>= 1) {
        mx = fmaxf(mx, __shfl_xor_sync(0xffffffffu, mx, o));
        cnt += __shfl_xor_sync(0xffffffffu, cnt, o);
    }
    if ((tid & 31) == 0) { smx[tid >> 5] = mx; scn[tid >> 5] = cnt; }
    __syncthreads();
    if (tid == 0) {
        float m = smx[0]; int c = scn[0];
#pragma unroll
        for (int w = 1; w < 8; w++) { m = fmaxf(m, smx[w]); c += scn[w]; }
        s_mx = m;
        rowcnt[b] = c;
    }
    __syncthreads();
    float m = s_mx;

    float se = 0.f;
    for (int j = tid; j < NCOLS; j += 256)
        se += __expf((row[j] - m) * 10.f);
#pragma unroll
    for (int o = 16; o; o >>= 1) se += __shfl_xor_sync(0xffffffffu, se, o);
    if ((tid & 31) == 0) ssm[tid >> 5] = se;
    __syncthreads();
    if (tid == 0) {
        float t = 0.f;
#pragma unroll
        for (int w = 0; w < 8; w++) t += ssm[w];
        rowlog[b] = (s - m) * 10.f - logf(t);
    }
}

// ---------------- final reduction ----------------
__global__ void k_final(const float* __restrict__ rowlog,
                        const int* __restrict__ rowcnt,
                        float* __restrict__ out) {
    int tid = threadIdx.x;  // 1024
    float lg = rowlog[tid];
    int c = rowcnt[tid];
    float a1 = (c < 1) ? 1.f : 0.f;
    float a3 = (c < 3) ? 1.f : 0.f;
    float a10 = (c < 10) ? 1.f : 0.f;

    __shared__ float s0[32], s1[32], s2[32], s3[32];
#pragma unroll
    for (int o = 16; o; o >>= 1) {
        lg  += __shfl_xor_sync(0xffffffffu, lg, o);
        a1  += __shfl_xor_sync(0xffffffffu, a1, o);
        a3  += __shfl_xor_sync(0xffffffffu, a3, o);
        a10 += __shfl_xor_sync(0xffffffffu, a10, o);
    }
    int wid = tid >> 5, lane = tid & 31;
    if (lane == 0) { s0[wid] = lg; s1[wid] = a1; s2[wid] = a3; s3[wid] = a10; }
    __syncthreads();
    if (wid == 0) {
        float v0 = s0[lane], v1 = s1[lane], v2 = s2[lane], v3 = s3[lane];
#pragma unroll
        for (int o = 16; o; o >>= 1) {
            v0 += __shfl_xor_sync(0xffffffffu, v0, o);
            v1 += __shfl_xor_sync(0xffffffffu, v1, o);
            v2 += __shfl_xor_sync(0xffffffffu, v2, o);
            v3 += __shfl_xor_sync(0xffffffffu, v3, o);
        }
        if (lane == 0) {
            out[0] = -v0 / (float)BATCH;
            out[1] = v1 / (float)BATCH;
            out[2] = v2 / (float)BATCH;
            out[3] = v3 / (float)BATCH;
        }
    }
}

// ---------------- launch ----------------
extern "C" void kernel_launch(void* const* d_in, const int* in_sizes, int n_in,
                              void* d_out, int out_size) {
    const float* z          = (const float*)d_in[0];
    const float* z_next     = (const float*)d_in[1];
    const float* z_next_hat = (const float*)d_in[2];
    const float* actions    = (const float*)d_in[3];
    const float* Wa         = (const float*)d_in[4];
    const float* ba         = (const float*)d_in[5];
    const float* W1         = (const float*)d_in[6];
    const float* b1         = (const float*)d_in[7];
    const float* W2         = (const float*)d_in[8];
    const float* b2         = (const float*)d_in[9];
    float* out = (float*)d_out;

    float *g, *zwb, *u, *simmat, *rowlog; int* rowcnt;
    __nv_bfloat16 *Af, *Az, *Ag, *Bf, *Bw1, *Bg;
    cudaGetSymbolAddress((void**)&g, d_g);
    cudaGetSymbolAddress((void**)&zwb, d_zwb);
    cudaGetSymbolAddress((void**)&u, d_u);
    cudaGetSymbolAddress((void**)&simmat, d_simmat);
    cudaGetSymbolAddress((void**)&rowlog, d_rowlog);
    cudaGetSymbolAddress((void**)&rowcnt, d_rowcnt);
    cudaGetSymbolAddress((void**)&Af, d_Af);
    cudaGetSymbolAddress((void**)&Az, d_Az);
    cudaGetSymbolAddress((void**)&Ag, d_Ag);
    cudaGetSymbolAddress((void**)&Bf, d_Bf);
    cudaGetSymbolAddress((void**)&Bw1, d_Bw1);
    cudaGetSymbolAddress((void**)&Bg, d_Bg);

    // 1. ha0 (+split) -> Ag
    k_ha0<<<BATCH, AH>>>(actions, Wa, ba, Ag);
    // 2. fp32 -> split-bf16 stacked conversions (incl. W1 transposes)
    k_conv<<<8320, 256>>>(z_next, z, z_next_hat, W2, W1, Af, Az, Bf, Bw1, Bg);
    // 3. all GEMMs via HMMA tensor cores (sim, u, zwb, g)
    k_mma<<<160, 256>>>(Af, Az, Ag, Bf, Bw1, Bg, b1, zwb, g, u, simmat);
    // 4. neg_sim columns
    k_neg<<<BATCH / NEG_BT, 256>>>(z, z_next, b2, zwb, g, u, simmat);
    // 5. per-row log-softmax + rank counts
    k_row<<<BATCH, 256>>>(simmat, rowlog, rowcnt);
    // 6. final outputs
    k_final<<<1, 1024>>>(rowlog, rowcnt, out);
}

// round 7
// speedup vs baseline: 2.2241x; 1.3822x over previous
#include <cuda_runtime.h>
#include <cuda_bf16.h>
#include <math.h>
#include <stdint.h>

// Problem constants
#define BATCH 1024
#define ZDIM  512
#define ADIM  8
#define AH    64
#define ZH    512
#define NNEG  100
#define NCOLS 1123
#define LDSIM 1152

// split-bf16 stacked K dims
#define KP    1536          // 3*512
#define KPG   192           // 3*64

// ---------------- device scratch ----------------
__device__ float d_g[BATCH * ZH];
__device__ float d_zwb[BATCH * ZH];
__device__ float d_u[BATCH * ZDIM];
__device__ float d_simmat[BATCH * LDSIM];
__device__ float d_rowlog[BATCH];
__device__ int   d_rowcnt[BATCH];

__device__ __nv_bfloat16 d_Af[BATCH * KP];     // z_next'  [Ah|Ah|Al]
__device__ __nv_bfloat16 d_Az[BATCH * KP];     // z'
__device__ __nv_bfloat16 d_Ag[BATCH * KPG];    // ha0'
__device__ __nv_bfloat16 d_Bf[1536 * KP];      // rows 0:1024 znh', 1024:1536 W2'  [Bh|Bl|Bh]
__device__ __nv_bfloat16 d_Bw1[512 * KP];      // W1[0:512]^T'
__device__ __nv_bfloat16 d_Bg[512 * KPG];      // W1[512:576]^T'

// ---------------- ha0 + split -> Ag ----------------
__global__ void k_ha0(const float* __restrict__ actions,
                      const float* __restrict__ Wa,
                      const float* __restrict__ ba,
                      __nv_bfloat16* __restrict__ Ag) {
    int b = blockIdx.x;
    int h = threadIdx.x;   // 64
    float s = ba[h];
#pragma unroll
    for (int a = 0; a < ADIM; a++)
        s += actions[b * ADIM + a] * Wa[a * AH + h];
    s = fmaxf(s, 0.f);
    __nv_bfloat16 hi = __float2bfloat16(s);
    __nv_bfloat16 lo = __float2bfloat16(s - __bfloat162float(hi));
    __nv_bfloat16* r = Ag + (size_t)b * KPG;
    r[h] = hi; r[64 + h] = hi; r[128 + h] = lo;   // A pattern [h|h|l]
}

// ---------------- conversions: fp32 -> split-bf16 stacked ----------------
__global__ void k_conv(const float* __restrict__ zn, const float* __restrict__ z,
                       const float* __restrict__ znh, const float* __restrict__ W2,
                       const float* __restrict__ W1,
                       __nv_bfloat16* __restrict__ Af, __nv_bfloat16* __restrict__ Az,
                       __nv_bfloat16* __restrict__ Bf, __nv_bfloat16* __restrict__ Bw1,
                       __nv_bfloat16* __restrict__ Bg) {
    int bid = blockIdx.x, tid = threadIdx.x;
    float v; __nv_bfloat16* r; int k;
    if (bid < 2048) {                 // Af <- z_next (A pattern)
        int e = bid * 256 + tid; int m = e >> 9; k = e & 511;
        v = zn[e]; r = Af + (size_t)m * KP;
        __nv_bfloat16 h = __float2bfloat16(v), l = __float2bfloat16(v - __bfloat162float(h));
        r[k] = h; r[512 + k] = h; r[1024 + k] = l; return;
    } else if (bid < 4096) {          // Az <- z (A pattern)
        int e = (bid - 2048) * 256 + tid; int m = e >> 9; k = e & 511;
        v = z[e]; r = Az + (size_t)m * KP;
        __nv_bfloat16 h = __float2bfloat16(v), l = __float2bfloat16(v - __bfloat162float(h));
        r[k] = h; r[512 + k] = h; r[1024 + k] = l; return;
    } else if (bid < 6144) {          // Bf rows 0:1024 <- z_next_hat (B pattern)
        int e = (bid - 4096) * 256 + tid; int m = e >> 9; k = e & 511;
        v = znh[e]; r = Bf + (size_t)m * KP;
    } else if (bid < 7168) {          // Bf rows 1024:1536 <- W2 (B pattern)
        int e = (bid - 6144) * 256 + tid; int n = e >> 9; k = e & 511;
        v = W2[e]; r = Bf + (size_t)(1024 + n) * KP;
    } else if (bid < 8192) {          // Bw1 <- W1[0:512]^T (B pattern)
        int e = (bid - 7168) * 256 + tid; int n = e >> 9; k = e & 511;
        v = W1[(size_t)k * ZH + n]; r = Bw1 + (size_t)n * KP;
    } else {                          // Bg <- W1[512:576]^T (B pattern, blocks of 64)
        int e = (bid - 8192) * 256 + tid; int n = e >> 6; k = e & 63;
        v = W1[(size_t)(512 + k) * ZH + n];
        __nv_bfloat16 h = __float2bfloat16(v), l = __float2bfloat16(v - __bfloat162float(h));
        r = Bg + (size_t)n * KPG;
        r[k] = h; r[64 + k] = l; r[128 + k] = h; return;
    }
    __nv_bfloat16 h = __float2bfloat16(v), l = __float2bfloat16(v - __bfloat162float(h));
    r[k] = h; r[512 + k] = l; r[1024 + k] = h;    // B pattern [h|l|h]
}

// ---------------- HMMA GEMM (unchanged from R5) ------------------
#define SM_PITCH 40

__device__ __forceinline__ void mma16816(float* d, const uint32_t* a, const uint32_t* b) {
    asm volatile(
        "mma.sync.aligned.m16n8k16.row.col.f32.bf16.bf16.f32 "
        "{%0,%1,%2,%3}, {%4,%5,%6,%7}, {%8,%9}, {%0,%1,%2,%3};"
        : "+f"(d[0]), "+f"(d[1]), "+f"(d[2]), "+f"(d[3])
        : "r"(a[0]), "r"(a[1]), "r"(a[2]), "r"(a[3]), "r"(b[0]), "r"(b[1]));
}
__device__ __forceinline__ void cpa16(const void* s, const void* gp) {
    uint32_t sa;
    asm("{ .reg .u64 t; cvta.to.shared.u64 t, %1; cvt.u32.u64 %0, t; }" : "=r"(sa) : "l"(s));
    asm volatile("cp.async.cg.shared.global [%0], [%1], 16;\n" :: "r"(sa), "l"(gp));
}

__global__ void __launch_bounds__(256, 1)
k_mma(const __nv_bfloat16* __restrict__ Af, const __nv_bfloat16* __restrict__ Az,
      const __nv_bfloat16* __restrict__ Ag, const __nv_bfloat16* __restrict__ Bf,
      const __nv_bfloat16* __restrict__ Bw1, const __nv_bfloat16* __restrict__ Bg,
      const float* __restrict__ b1,
      float* __restrict__ zwb, float* __restrict__ g,
      float* __restrict__ u, float* __restrict__ simmat) {
    __shared__ __align__(16) __nv_bfloat16 As[2][128][SM_PITCH];
    __shared__ __align__(16) __nv_bfloat16 Bs[2][128][SM_PITCH];

    const int tid = threadIdx.x;          // 256
    const int lane = tid & 31, warp = tid >> 5;
    const int grp = lane >> 2, qid = lane & 3;
    const int wm = warp >> 2, wn = warp & 3;   // 2 x 4 warp grid

    const __nv_bfloat16 *Aseg, *Bseg;
    float* Cseg; const float* bias = nullptr;
    int ldk, T, m0, ldc, ccol0;
    {
        int bid = blockIdx.x;
        if (bid < 96) {
            int mt = bid / 12, nt = bid % 12;
            m0 = mt * 128; Aseg = Af; ldk = KP; T = 48;
            Bseg = Bf + (size_t)nt * 128 * KP;
            if (nt < 8) { Cseg = simmat; ldc = LDSIM; ccol0 = nt * 128; }
            else        { Cseg = u;      ldc = ZDIM;  ccol0 = (nt - 8) * 128; }
        } else if (bid < 128) {
            int t = bid - 96; int mt = t >> 2, nt = t & 3;
            m0 = mt * 128; Aseg = Az; ldk = KP; T = 48;
            Bseg = Bw1 + (size_t)nt * 128 * KP;
            Cseg = zwb; ldc = ZH; ccol0 = nt * 128; bias = b1;
        } else {
            int t = bid - 128; int mt = t >> 2, nt = t & 3;
            m0 = mt * 128; Aseg = Ag; ldk = KPG; T = 6;
            Bseg = Bg + (size_t)nt * 128 * KPG;
            Cseg = g; ldc = ZH; ccol0 = nt * 128;
        }
    }

    float acc[4][4][4];
#pragma unroll
    for (int i = 0; i < 4; i++)
#pragma unroll
        for (int j = 0; j < 4; j++)
#pragma unroll
            for (int q = 0; q < 4; q++) acc[i][j][q] = 0.f;

    auto load_chunk = [&](int chunk, int st) {
#pragma unroll
        for (int it = 0; it < 2; it++) {
            int idx = it * 256 + tid;
            int row = idx >> 2, seg = (idx & 3) * 8;
            cpa16(&As[st][row][seg], Aseg + (size_t)(m0 + row) * ldk + chunk * 32 + seg);
        }
#pragma unroll
        for (int it = 0; it < 2; it++) {
            int idx = it * 256 + tid;
            int row = idx >> 2, seg = (idx & 3) * 8;
            cpa16(&Bs[st][row][seg], Bseg + (size_t)row * ldk + chunk * 32 + seg);
        }
        asm volatile("cp.async.commit_group;\n" ::: "memory");
    };

    load_chunk(0, 0);

    for (int t = 0; t < T; t++) {
        const int s = t & 1;
        if (t + 1 < T) load_chunk(t + 1, 1 - s);
        if (t + 1 < T) asm volatile("cp.async.wait_group 1;\n" ::: "memory");
        else           asm volatile("cp.async.wait_group 0;\n" ::: "memory");
        __syncthreads();

#pragma unroll
        for (int ks = 0; ks < 2; ks++) {
            const int kofs = ks * 16 + qid * 2;
            uint32_t afr[4][4], bfr[4][2];
#pragma unroll
            for (int mi = 0; mi < 4; mi++) {
                int r0 = wm * 64 + mi * 16 + grp;
                afr[mi][0] = *(const uint32_t*)&As[s][r0][kofs];
                afr[mi][1] = *(const uint32_t*)&As[s][r0 + 8][kofs];
                afr[mi][2] = *(const uint32_t*)&As[s][r0][kofs + 8];
                afr[mi][3] = *(const uint32_t*)&As[s][r0 + 8][kofs + 8];
            }
#pragma unroll
            for (int ni = 0; ni < 4; ni++) {
                int nr = wn * 32 + ni * 8 + grp;
                bfr[ni][0] = *(const uint32_t*)&Bs[s][nr][kofs];
                bfr[ni][1] = *(const uint32_t*)&Bs[s][nr][kofs + 8];
            }
#pragma unroll
            for (int mi = 0; mi < 4; mi++)
#pragma unroll
                for (int ni = 0; ni < 4; ni++)
                    mma16816(acc[mi][ni], afr[mi], bfr[ni]);
        }
        __syncthreads();
    }

#pragma unroll
    for (int mi = 0; mi < 4; mi++) {
        int m = m0 + wm * 64 + mi * 16 + grp;
#pragma unroll
        for (int ni = 0; ni < 4; ni++) {
            int n = ccol0 + wn * 32 + ni * 8 + qid * 2;
            float bx = 0.f, by = 0.f;
            if (bias) { bx = bias[n]; by = bias[n + 1]; }
            *(float2*)&Cseg[(size_t)m * ldc + n] =
                make_float2(acc[mi][ni][0] + bx, acc[mi][ni][1] + by);
            *(float2*)&Cseg[(size_t)(m + 8) * ldc + n] =
                make_float2(acc[mi][ni][2] + bx, acc[mi][ni][3] + by);
        }
    }
}

// ---------------- neg_sim v2: smem-tiled g reuse ----------------
// Block = 8 batch rows x one i-half. grid = 256.
//   bid>>1 -> b-tile (b0 = 8*that), bid&1 -> i-half: [1,50) or [50,100)
// Warp w owns b = b0+w; lanes map to i = ibase+lane (+32 for acc2).
// g rows b0+ibase .. b0+ibase+56 staged in smem transposed gs[k][row].
#define KC 64
__global__ void __launch_bounds__(256, 4)
k_neg(const float* __restrict__ z, const float* __restrict__ zn,
      const float* __restrict__ b2,
      const float* __restrict__ zwb, const float* __restrict__ g,
      const float* __restrict__ u, float* __restrict__ simmat) {
    const int ihalf = blockIdx.x & 1;
    const int b0 = (blockIdx.x >> 1) * 8;
    const int ibase = 1 + ihalf * 49;        // 1..49 | 50..99
    const int icount = 49 + ihalf;
    const int tid = threadIdx.x, w = tid >> 5, lane = tid & 31;
    const int b = b0 + w;

    __shared__ float zc[8][KC];
    __shared__ float uc[8][KC];
    __shared__ float gs[KC][73];             // 73-pitch; rows up to 70 read (padded)

    // base = (z[b]+b2) . zn[b], butterfly-reduced so all lanes hold it
    float base = 0.f;
    {
        const float4* z4 = (const float4*)(z + (size_t)b * ZDIM);
        const float4* zn4 = (const float4*)(zn + (size_t)b * ZDIM);
        const float4* b24 = (const float4*)b2;
#pragma unroll
        for (int k4 = lane; k4 < 128; k4 += 32) {
            float4 a = z4[k4], c = zn4[k4], d = b24[k4];
            base += (a.x + d.x) * c.x + (a.y + d.y) * c.y
                  + (a.z + d.z) * c.z + (a.w + d.w) * c.w;
        }
#pragma unroll
        for (int o = 16; o; o >>= 1) base += __shfl_xor_sync(0xffffffffu, base, o);
    }

    float acc1 = 0.f, acc2 = 0.f;
    const int r1 = w + lane, r2 = r1 + 32;

    for (int kc = 0; kc < ZDIM; kc += KC) {
        __syncthreads();
        // zwb/u chunk: threads 0-127 -> zc, 128-255 -> uc (8 rows x 16 float4)
        {
            int idx = tid & 127;
            int row = idx >> 4, k4 = idx & 15;
            const float4* src = (tid < 128) ? (const float4*)zwb : (const float4*)u;
            float4 v = src[(size_t)(b0 + row) * 128 + (kc >> 2) + k4];
            float* dst = (tid < 128) ? &zc[row][k4 * 4] : &uc[row][k4 * 4];
            *(float4*)dst = v;
        }
        // g chunk: 57 rows x 16 float4, transposed into gs[k][row]
        for (int idx = tid; idx < 57 * 16; idx += 256) {
            int k4 = idx / 57, row = idx - k4 * 57;
            int gr = (b0 + ibase + row) & (BATCH - 1);
            float4 v = ((const float4*)g)[(size_t)gr * 128 + (kc >> 2) + k4];
            gs[k4 * 4 + 0][row] = v.x;
            gs[k4 * 4 + 1][row] = v.y;
            gs[k4 * 4 + 2][row] = v.z;
            gs[k4 * 4 + 3][row] = v.w;
        }
        __syncthreads();
#pragma unroll 8
        for (int k = 0; k < KC; k++) {
            float zv = zc[w][k], uv = uc[w][k];
            acc1 += fmaxf(zv + gs[k][r1], 0.f) * uv;
            acc2 += fmaxf(zv + gs[k][r2], 0.f) * uv;
        }
    }

    float* orow = simmat + (size_t)b * LDSIM + (BATCH - 1);
    orow[ibase + lane] = base + acc1;                 // icount >= 32, always valid
    if (lane + 32 < icount)
        orow[ibase + lane + 32] = base + acc2;
}

// ---------------- per-row single-pass online softmax + rank count ----------------
__global__ void k_row(const float* __restrict__ simmat,
                      float* __restrict__ rowlog, int* __restrict__ rowcnt) {
    int b = blockIdx.x;
    int tid = threadIdx.x;   // 256
    const float* row = simmat + (size_t)b * LDSIM;
    float s = row[b];

    float mx = -INFINITY, se = 0.f;
    int cnt = 0;
    for (int j = tid; j < NCOLS; j += 256) {
        float v = row[j];
        cnt += (v > s) || (v == s && j < b);
        float nm = fmaxf(mx, v);
        se = se * __expf((mx - nm) * 10.f) + __expf((v - nm) * 10.f);
        mx = nm;
    }
#pragma unroll
    for (int o = 16; o; o >>= 1) {
        float om = __shfl_xor_sync(0xffffffffu, mx, o);
        float os = __shfl_xor_sync(0xffffffffu, se, o);
        cnt += __shfl_xor_sync(0xffffffffu, cnt, o);
        float nm = fmaxf(mx, om);
        se = se * __expf((mx - nm) * 10.f) + os * __expf((om - nm) * 10.f);
        mx = nm;
    }
    __shared__ float smx[8], ssm[8];
    __shared__ int scn[8];
    if ((tid & 31) == 0) { smx[tid >> 5] = mx; ssm[tid >> 5] = se; scn[tid >> 5] = cnt; }
    __syncthreads();
    if (tid == 0) {
        float m = smx[0], t = ssm[0]; int c = scn[0];
#pragma unroll
        for (int wv = 1; wv < 8; wv++) {
            float om = smx[wv], os = ssm[wv];
            float nm = fmaxf(m, om);
            t = t * __expf((m - nm) * 10.f) + os * __expf((om - nm) * 10.f);
            m = nm;
            c += scn[wv];
        }
        rowlog[b] = (s - m) * 10.f - logf(t);
        rowcnt[b] = c;
    }
}

// ---------------- final reduction ----------------
__global__ void k_final(const float* __restrict__ rowlog,
                        const int* __restrict__ rowcnt,
                        float* __restrict__ out) {
    int tid = threadIdx.x;  // 1024
    float lg = rowlog[tid];
    int c = rowcnt[tid];
    float a1 = (c < 1) ? 1.f : 0.f;
    float a3 = (c < 3) ? 1.f : 0.f;
    float a10 = (c < 10) ? 1.f : 0.f;

    __shared__ float s0[32], s1[32], s2[32], s3[32];
#pragma unroll
    for (int o = 16; o; o >>= 1) {
        lg  += __shfl_xor_sync(0xffffffffu, lg, o);
        a1  += __shfl_xor_sync(0xffffffffu, a1, o);
        a3  += __shfl_xor_sync(0xffffffffu, a3, o);
        a10 += __shfl_xor_sync(0xffffffffu, a10, o);
    }
    int wid = tid >> 5, lane = tid & 31;
    if (lane == 0) { s0[wid] = lg; s1[wid] = a1; s2[wid] = a3; s3[wid] = a10; }
    __syncthreads();
    if (wid == 0) {
        float v0 = s0[lane], v1 = s1[lane], v2 = s2[lane], v3 = s3[lane];
#pragma unroll
        for (int o = 16; o; o >>= 1) {
            v0 += __shfl_xor_sync(0xffffffffu, v0, o);
            v1 += __shfl_xor_sync(0xffffffffu, v1, o);
            v2 += __shfl_xor_sync(0xffffffffu, v2, o);
            v3 += __shfl_xor_sync(0xffffffffu, v3, o);
        }
        if (lane == 0) {
            out[0] = -v0 / (float)BATCH;
            out[1] = v1 / (float)BATCH;
            out[2] = v2 / (float)BATCH;
            out[3] = v3 / (float)BATCH;
        }
    }
}

// ---------------- launch ----------------
extern "C" void kernel_launch(void* const* d_in, const int* in_sizes, int n_in,
                              void* d_out, int out_size) {
    const float* z          = (const float*)d_in[0];
    const float* z_next     = (const float*)d_in[1];
    const float* z_next_hat = (const float*)d_in[2];
    const float* actions    = (const float*)d_in[3];
    const float* Wa         = (const float*)d_in[4];
    const float* ba         = (const float*)d_in[5];
    const float* W1         = (const float*)d_in[6];
    const float* b1         = (const float*)d_in[7];
    const float* W2         = (const float*)d_in[8];
    const float* b2         = (const float*)d_in[9];
    float* out = (float*)d_out;

    float *g, *zwb, *u, *simmat, *rowlog; int* rowcnt;
    __nv_bfloat16 *Af, *Az, *Ag, *Bf, *Bw1, *Bg;
    cudaGetSymbolAddress((void**)&g, d_g);
    cudaGetSymbolAddress((void**)&zwb, d_zwb);
    cudaGetSymbolAddress((void**)&u, d_u);
    cudaGetSymbolAddress((void**)&simmat, d_simmat);
    cudaGetSymbolAddress((void**)&rowlog, d_rowlog);
    cudaGetSymbolAddress((void**)&rowcnt, d_rowcnt);
    cudaGetSymbolAddress((void**)&Af, d_Af);
    cudaGetSymbolAddress((void**)&Az, d_Az);
    cudaGetSymbolAddress((void**)&Ag, d_Ag);
    cudaGetSymbolAddress((void**)&Bf, d_Bf);
    cudaGetSymbolAddress((void**)&Bw1, d_Bw1);
    cudaGetSymbolAddress((void**)&Bg, d_Bg);

    // 1. ha0 (+split) -> Ag
    k_ha0<<<BATCH, AH>>>(actions, Wa, ba, Ag);
    // 2. fp32 -> split-bf16 stacked conversions (incl. W1 transposes)
    k_conv<<<8320, 256>>>(z_next, z, z_next_hat, W2, W1, Af, Az, Bf, Bw1, Bg);
    // 3. all GEMMs via HMMA tensor cores (sim, u, zwb, g)
    k_mma<<<160, 256>>>(Af, Az, Ag, Bf, Bw1, Bg, b1, zwb, g, u, simmat);
    // 4. neg_sim columns (smem-tiled)
    k_neg<<<256, 256>>>(z, z_next, b2, zwb, g, u, simmat);
    // 5. per-row single-pass softmax + rank counts
    k_row<<<BATCH, 256>>>(simmat, rowlog, rowcnt);
    // 6. final outputs
    k_final<<<1, 1024>>>(rowlog, rowcnt, out);
}